// round 9
// baseline (speedup 1.0000x reference)
#include <cuda_runtime.h>
#include <cstdint>

// BidirectionalLSTMComplex: S=1024, B=2048, H=32, IN=1, OUT=1
// Round 9 (= round 8 + missing <cstdint>): decoupled halves via SMEM mbarrier
// rings (phase-correct). B runs tau=t-1; cross waits at distance 2.
// hf1 = depth-8 ring. Internal sync: named 128-thread barriers.

#define S_LEN 1024
#define B_TOT 2048
#define HID   32
#define GATES 128
#define NB    7
#define NCTA  296
#define HP    36

typedef unsigned long long u64;

__device__ __forceinline__ void fma2(u64 &acc, u64 a, u64 b) {
    asm("fma.rn.f32x2 %0, %1, %2, %3;" : "=l"(acc) : "l"(a), "l"(b), "l"(acc));
}
__device__ __forceinline__ void add2(u64 &a, u64 b) {
    asm("add.rn.f32x2 %0, %1, %2;" : "=l"(a) : "l"(a), "l"(b));
}
__device__ __forceinline__ float hsum2(u64 v) {
    float lo, hi;
    asm("mov.b64 {%0,%1}, %2;" : "=f"(lo), "=f"(hi) : "l"(v));
    return lo + hi;
}
__device__ __forceinline__ float tanh_fast(float x) {
    float y;
    asm("tanh.approx.f32 %0, %1;" : "=f"(y) : "f"(x));
    return y;
}
__device__ __forceinline__ float sigm(float x) {
    return fmaf(tanh_fast(x * 0.5f), 0.5f, 0.5f);
}

__device__ __forceinline__ uint32_t s2u(const void *p) {
    uint32_t a;
    asm("{ .reg .u64 t; cvta.to.shared.u64 t, %1; cvt.u32.u64 %0, t; }"
        : "=r"(a) : "l"(p));
    return a;
}
__device__ __forceinline__ void mb_init(uint32_t a, uint32_t cnt) {
    asm volatile("mbarrier.init.shared.b64 [%0], %1;" :: "r"(a), "r"(cnt) : "memory");
}
__device__ __forceinline__ void mb_arrive(uint32_t a) {
    asm volatile("mbarrier.arrive.shared.b64 _, [%0];" :: "r"(a) : "memory");
}
__device__ __forceinline__ void mb_wait(uint32_t a, uint32_t parity) {
    uint32_t done;
    asm volatile(
        "{\n\t.reg .pred p;\n\t"
        "mbarrier.try_wait.parity.acquire.cta.shared::cta.b64 p, [%1], %2;\n\t"
        "selp.b32 %0, 1, 0, p;\n\t}"
        : "=r"(done) : "r"(a), "r"(parity) : "memory");
    if (!done) {
        asm volatile(
            "{\n\t.reg .pred P1;\n\t"
            "WL_%=:\n\t"
            "mbarrier.try_wait.parity.acquire.cta.shared::cta.b64 P1, [%0], %1, 0x989680;\n\t"
            "@P1 bra.uni WD_%=;\n\t"
            "bra.uni WL_%=;\n\t"
            "WD_%=:\n\t}"
            :: "r"(a), "r"(parity) : "memory");
    }
}

__device__ __forceinline__ void load_row(u64 *w, const float *base) {
    const ulonglong2 *p = (const ulonglong2 *)base;
#pragma unroll
    for (int i = 0; i < 8; i++) {
        ulonglong2 q = p[i];
        w[2 * i]     = q.x;
        w[2 * i + 1] = q.y;
    }
}

__device__ __forceinline__ void cell1(const float *g, float *c, float *h, int m) {
    float gi = g[m], gf = g[m + 32], gg = g[m + 64], go = g[m + 96];
    float c2 = sigm(gf) * c[m] + sigm(gi) * tanh_fast(gg);
    c[m] = c2;
    h[m] = sigm(go) * tanh_fast(c2);
}

__device__ __forceinline__ void cell2(const float *g0, float *c0, float *h0,
                                      const float *g1, float *c1, float *h1, int m) {
    float ai = g0[m], af = g0[m + 32], ag = g0[m + 64], ao = g0[m + 96];
    float bi = g1[m], bf = g1[m + 32], bg = g1[m + 64], bo = g1[m + 96];
    float sfa = sigm(af), sfb = sigm(bf);
    float sia = sigm(ai), sib = sigm(bi);
    float tga = tanh_fast(ag), tgb = tanh_fast(bg);
    float soa = sigm(ao), sob = sigm(bo);
    float c2a = sfa * c0[m] + sia * tga;
    float c2b = sfb * c1[m] + sib * tgb;
    c0[m] = c2a; c1[m] = c2b;
    h0[m] = soa * tanh_fast(c2a);
    h1[m] = sob * tanh_fast(c2b);
}

#define BAR_F() asm volatile("bar.sync 1, 128;" ::: "memory")
#define BAR_B() asm volatile("bar.sync 2, 128;" ::: "memory")

__global__ void __launch_bounds__(256, 2)
lstm_kernel(const float *__restrict__ x,
            const float *__restrict__ Wih_f0, const float *__restrict__ Whh_f0, const float *__restrict__ b_f0,
            const float *__restrict__ Wih_f1, const float *__restrict__ Whh_f1, const float *__restrict__ b_f1,
            const float *__restrict__ Wih_b0, const float *__restrict__ Whh_b0, const float *__restrict__ b_b0,
            const float *__restrict__ Wih_b1, const float *__restrict__ Whh_b1, const float *__restrict__ b_b1,
            const float *__restrict__ Wlin,   const float *__restrict__ blin,
            const int *__restrict__ future_p,
            float *__restrict__ out)
{
    const int tid  = threadIdx.x;
    const int j    = tid & 127;
    const bool isF = tid < 128;
    const int nb0  = blockIdx.x * NB;

    __shared__ __align__(16) float hf0s[NB][HP];
    __shared__ __align__(16) float hf1s[8][NB][HP];   // cross-half ring
    __shared__ __align__(16) float hb0s[NB][HP];
    __shared__ __align__(16) float hb1s[2][NB][HP];
    __shared__ float cf0s[NB][HID], cf1s[NB][HID], cb0s[NB][HID], cb1s[NB][HID];
    __shared__ float gF0[NB][GATES], gF1[NB][GATES];
    __shared__ float gB0[NB][GATES], gB1[NB][GATES];
    __shared__ float xs[NB], xbs[NB];
    __shared__ __align__(16) float wls[2 * HID];
    __shared__ float blin_s;
    __shared__ __align__(8) u64 mbF[4], mbB[4];       // completion rings

    u64 w0[16], w1[16], w2[16];
    float bias0, bias1, wx;
    if (isF) {
        load_row(w0, Whh_f0 + j * HID);
        load_row(w1, Wih_f1 + j * HID);
        load_row(w2, Whh_f1 + j * HID);
        bias0 = b_f0[j]; bias1 = b_f1[j]; wx = Wih_f0[j];
    } else {
        load_row(w0, Whh_b0 + j * HID);
        load_row(w1, Wih_b1 + j * HID);
        load_row(w2, Whh_b1 + j * HID);   // on hf1 (replicated bug)
        bias0 = b_b0[j]; bias1 = b_b1[j]; wx = Wih_b0[j];
    }
    const int fut = future_p[0];
    const float *xbase = x + nb0;
    const bool jval = (j < NB) && (nb0 + j < B_TOT);

    const uint32_t mbF_a = s2u(mbF), mbB_a = s2u(mbB);

    if (tid == 0) {
#pragma unroll
        for (int i = 0; i < 4; i++) {
            mb_init(mbF_a + 8 * i, 128);
            mb_init(mbB_a + 8 * i, 128);
        }
    }

    for (int i = tid; i < NB * HP; i += 256) {
        ((float *)hf0s)[i] = 0.f; ((float *)hb0s)[i] = 0.f;
    }
    for (int i = tid; i < 8 * NB * HP; i += 256) ((float *)hf1s)[i] = 0.f;
    for (int i = tid; i < 2 * NB * HP; i += 256) ((float *)hb1s)[i] = 0.f;
    for (int i = tid; i < NB * HID; i += 256) {
        ((float *)cf0s)[i] = 0.f; ((float *)cf1s)[i] = 0.f;
        ((float *)cb0s)[i] = 0.f; ((float *)cb1s)[i] = 0.f;
    }
    if (tid < 2 * HID) wls[tid] = Wlin[tid];
    if (tid == 128) blin_s = blin[0];

    int rb = fut % S_LEN; if (rb < 0) rb += S_LEN;     // backward index for tau=0

    if (tid < NB) {
        xs[tid] = jval ? xbase[tid] : 0.f;
    } else if (tid >= 128 && tid < 128 + NB) {
        xbs[tid - 128] = jval ? xbase[rb * B_TOT + (tid - 128)] : 0.f;
    }
    rb--; if (rb < 0) rb += S_LEN;                     // index for tau=1

    __syncthreads();

    const int m  = j & 31;
    const int ng = j >> 5;

    // prologue: f0_0 from zero state
    if (isF) {
#pragma unroll
        for (int n = 0; n < NB; n++) gF0[n][j] = bias0 + wx * xs[n];
    }
    __syncthreads();
    if (isF) {
        if (ng < 3) cell2(gF0[ng], cf0s[ng], hf0s[ng],
                          gF0[ng + 4], cf0s[ng + 4], hf0s[ng + 4], m);
        else        cell1(gF0[3], cf0s[3], hf0s[3], m);
    }
    if (tid < NB) xs[tid] = jval ? xbase[B_TOT + tid] : 0.f;   // x_1
    __syncthreads();

    // F iter t: f0_{t+1}, f1_t.  B iter t: tau=t-1: b0_tau, b1_{tau-1}, out_{tau-2}.
    for (int t = 0; t < S_LEN + 3; t++) {
        if (isF) {
            if (t >= 1) BAR_F();                                // finalize(t-1) -> compute(t)
            if (t >= 2) mb_wait(mbB_a + 8 * ((t - 2) & 3), ((t - 2) >> 2) & 1);

            float xreg = 0.f;
            if (t < S_LEN) {
                if (jval && t + 2 < S_LEN) xreg = xbase[(t + 2) * B_TOT + j];
#pragma unroll 1
                for (int n = 0; n < NB; n++) {
                    u64 a0 = 0, a1 = 0, a2 = 0, a3 = 0, a4 = 0, a5 = 0;
                    const ulonglong2 *hu = (const ulonglong2 *)hf0s[n];
                    const ulonglong2 *hv = (const ulonglong2 *)hf1s[(t - 1) & 7][n];
#pragma unroll
                    for (int c = 0; c < 8; c++) {
                        ulonglong2 u = hu[c];
                        fma2(a0, w0[2 * c],     u.x);
                        fma2(a1, w0[2 * c + 1], u.y);
                        fma2(a2, w1[2 * c],     u.x);
                        fma2(a3, w1[2 * c + 1], u.y);
                        ulonglong2 v = hv[c];
                        fma2(a4, w2[2 * c],     v.x);
                        fma2(a5, w2[2 * c + 1], v.y);
                    }
                    add2(a0, a1);
                    gF0[n][j] = hsum2(a0) + bias0 + wx * xs[n];     // f0_{t+1}
                    add2(a2, a3); add2(a4, a5); add2(a2, a4);
                    gF1[n][j] = hsum2(a2) + bias1;                  // f1_t
                }
            }
            BAR_F();                                            // gates ready
            if (t < S_LEN) {
                if (ng < 3) {
                    cell2(gF0[ng], cf0s[ng], hf0s[ng],
                          gF0[ng + 4], cf0s[ng + 4], hf0s[ng + 4], m);
                    cell2(gF1[ng], cf1s[ng], hf1s[t & 7][ng],
                          gF1[ng + 4], cf1s[ng + 4], hf1s[t & 7][ng + 4], m);
                } else {
                    cell2(gF0[3], cf0s[3], hf0s[3],
                          gF1[3], cf1s[3], hf1s[t & 7][3], m);
                }
                if (j < NB) xs[j] = xreg;
            }
            mb_arrive(mbF_a + 8 * (t & 3));                     // publish "F done t"
        } else {
            if (t >= 1) BAR_B();
            if (t >= 2) mb_wait(mbF_a + 8 * ((t - 2) & 3), ((t - 2) >> 2) & 1);

            const int tau = t - 1;
            float xbreg = 0.f;
            if (t >= 1) {
                if (tau <= S_LEN) {
                    if (jval && tau + 1 < S_LEN) xbreg = xbase[rb * B_TOT + j];
#pragma unroll 1
                    for (int n = 0; n < NB; n++) {
                        u64 a0 = 0, a1 = 0, a2 = 0, a3 = 0, a4 = 0, a5 = 0;
                        const ulonglong2 *hu = (const ulonglong2 *)hb0s[n];
                        const ulonglong2 *hv = (const ulonglong2 *)hf1s[(tau - 1) & 7][n];
#pragma unroll
                        for (int c = 0; c < 8; c++) {
                            ulonglong2 u = hu[c];
                            fma2(a0, w0[2 * c],     u.x);
                            fma2(a1, w0[2 * c + 1], u.y);
                            fma2(a2, w1[2 * c],     u.x);
                            fma2(a3, w1[2 * c + 1], u.y);
                            ulonglong2 v = hv[c];
                            fma2(a4, w2[2 * c],     v.x);
                            fma2(a5, w2[2 * c + 1], v.y);
                        }
                        add2(a0, a1);
                        gB0[n][j] = hsum2(a0) + bias0 + wx * xbs[n];    // b0_tau
                        add2(a2, a3); add2(a4, a5); add2(a2, a4);
                        gB1[n][j] = hsum2(a2) + bias1;                  // b1_{tau-1}
                    }
                }
                // out_{tau-2}: hf1_{tau-2} (covered by wait), hb1_{tau-2} (own)
                if (tau >= 2 && j >= 120) {
                    int n = j - 120;
                    if (n < NB && nb0 + n < B_TOT) {
                        const ulonglong2 *pf = (const ulonglong2 *)hf1s[(tau - 2) & 7][n];
                        const ulonglong2 *pk = (const ulonglong2 *)hb1s[tau & 1][n];
                        const ulonglong2 *wf = (const ulonglong2 *)wls;
                        u64 acc = 0, acc2 = 0;
#pragma unroll
                        for (int c = 0; c < 8; c++) {
                            ulonglong2 u = pf[c], wu = wf[c];
                            fma2(acc,  wu.x, u.x);
                            fma2(acc2, wu.y, u.y);
                            ulonglong2 v = pk[c], wv = wf[c + 8];
                            fma2(acc,  wv.x, v.x);
                            fma2(acc2, wv.y, v.y);
                        }
                        add2(acc, acc2);
                        out[(nb0 + n) * S_LEN + (tau - 2)] = hsum2(acc) + blin_s;
                    }
                }
                rb--; if (rb < 0) rb += S_LEN;
            }
            BAR_B();                                            // gates ready
            if (t >= 1) {
                if (tau < S_LEN) {
                    if (ng < 3) cell2(gB0[ng], cb0s[ng], hb0s[ng],
                                      gB0[ng + 4], cb0s[ng + 4], hb0s[ng + 4], m);
                    else        cell1(gB0[3], cb0s[3], hb0s[3], m);
                    if (j < NB) xbs[j] = xbreg;
                }
                if (tau >= 1 && tau <= S_LEN) {
                    const int sb = (tau + 1) & 1;   // (tau-1)&1
                    if (ng < 3) cell2(gB1[ng], cb1s[ng], hb1s[sb][ng],
                                      gB1[ng + 4], cb1s[ng + 4], hb1s[sb][ng + 4], m);
                    else        cell1(gB1[3], cb1s[3], hb1s[sb][3], m);
                }
            }
            mb_arrive(mbB_a + 8 * (t & 3));                     // publish "B done t"
        }
    }
}

extern "C" void kernel_launch(void *const *d_in, const int *in_sizes, int n_in,
                              void *d_out, int out_size)
{
    const float *x      = (const float *)d_in[0];
    const float *Wih_f0 = (const float *)d_in[1];
    const float *Whh_f0 = (const float *)d_in[2];
    const float *b_f0   = (const float *)d_in[3];
    const float *Wih_f1 = (const float *)d_in[4];
    const float *Whh_f1 = (const float *)d_in[5];
    const float *b_f1   = (const float *)d_in[6];
    const float *Wih_b0 = (const float *)d_in[7];
    const float *Whh_b0 = (const float *)d_in[8];
    const float *b_b0   = (const float *)d_in[9];
    const float *Wih_b1 = (const float *)d_in[10];
    const float *Whh_b1 = (const float *)d_in[11];
    const float *b_b1   = (const float *)d_in[12];
    const float *Wlin   = (const float *)d_in[13];
    const float *blin   = (const float *)d_in[14];
    const int   *future = (const int *)d_in[15];
    float *out = (float *)d_out;

    lstm_kernel<<<NCTA, 256>>>(x,
                               Wih_f0, Whh_f0, b_f0,
                               Wih_f1, Whh_f1, b_f1,
                               Wih_b0, Whh_b0, b_b0,
                               Wih_b1, Whh_b1, b_b1,
                               Wlin, blin, future, out);
}

// round 10
// speedup vs baseline: 1.1781x; 1.1781x over previous
#include <cuda_runtime.h>

// BidirectionalLSTMComplex: S=1024, B=2048, H=32, IN=1, OUT=1
// Round 10: round-6 structure (best: 3380us), compute n-loops FULLY unrolled
// so ptxas can software-pipeline LDS of iteration n+1 under FMAs of n.

#define S_LEN 1024
#define B_TOT 2048
#define HID   32
#define GATES 128
#define NB    7
#define NCTA  296
#define HP    36

typedef unsigned long long u64;

__device__ __forceinline__ void fma2(u64 &acc, u64 a, u64 b) {
    asm("fma.rn.f32x2 %0, %1, %2, %3;" : "=l"(acc) : "l"(a), "l"(b), "l"(acc));
}
__device__ __forceinline__ void add2(u64 &a, u64 b) {
    asm("add.rn.f32x2 %0, %1, %2;" : "=l"(a) : "l"(a), "l"(b));
}
__device__ __forceinline__ float hsum2(u64 v) {
    float lo, hi;
    asm("mov.b64 {%0,%1}, %2;" : "=f"(lo), "=f"(hi) : "l"(v));
    return lo + hi;
}
__device__ __forceinline__ float tanh_fast(float x) {
    float y;
    asm("tanh.approx.f32 %0, %1;" : "=f"(y) : "f"(x));
    return y;
}
__device__ __forceinline__ float sigm(float x) {
    return fmaf(tanh_fast(x * 0.5f), 0.5f, 0.5f);
}

__device__ __forceinline__ void load_row(u64 *w, const float *base) {
    const ulonglong2 *p = (const ulonglong2 *)base;
#pragma unroll
    for (int i = 0; i < 8; i++) {
        ulonglong2 q = p[i];
        w[2 * i]     = q.x;
        w[2 * i + 1] = q.y;
    }
}

__device__ __forceinline__ void cell1(const float *g, float *c, float *h, int m) {
    float gi = g[m], gf = g[m + 32], gg = g[m + 64], go = g[m + 96];
    float c2 = sigm(gf) * c[m] + sigm(gi) * tanh_fast(gg);
    c[m] = c2;
    h[m] = sigm(go) * tanh_fast(c2);
}

__device__ __forceinline__ void cell2(const float *g0, float *c0, float *h0,
                                      const float *g1, float *c1, float *h1, int m) {
    float ai = g0[m], af = g0[m + 32], ag = g0[m + 64], ao = g0[m + 96];
    float bi = g1[m], bf = g1[m + 32], bg = g1[m + 64], bo = g1[m + 96];
    float sfa = sigm(af), sfb = sigm(bf);
    float sia = sigm(ai), sib = sigm(bi);
    float tga = tanh_fast(ag), tgb = tanh_fast(bg);
    float soa = sigm(ao), sob = sigm(bo);
    float c2a = sfa * c0[m] + sia * tga;
    float c2b = sfb * c1[m] + sib * tgb;
    c0[m] = c2a; c1[m] = c2b;
    h0[m] = soa * tanh_fast(c2a);
    h1[m] = sob * tanh_fast(c2b);
}

__global__ void __launch_bounds__(256, 2)
lstm_kernel(const float *__restrict__ x,
            const float *__restrict__ Wih_f0, const float *__restrict__ Whh_f0, const float *__restrict__ b_f0,
            const float *__restrict__ Wih_f1, const float *__restrict__ Whh_f1, const float *__restrict__ b_f1,
            const float *__restrict__ Wih_b0, const float *__restrict__ Whh_b0, const float *__restrict__ b_b0,
            const float *__restrict__ Wih_b1, const float *__restrict__ Whh_b1, const float *__restrict__ b_b1,
            const float *__restrict__ Wlin,   const float *__restrict__ blin,
            const int *__restrict__ future_p,
            float *__restrict__ out)
{
    const int tid  = threadIdx.x;
    const int j    = tid & 127;
    const bool isF = tid < 128;
    const int nb0  = blockIdx.x * NB;

    __shared__ __align__(16) float hf0s[NB][HP];
    __shared__ __align__(16) float hf1s[2][NB][HP];
    __shared__ __align__(16) float hb0s[NB][HP];
    __shared__ __align__(16) float hb1s[2][NB][HP];
    __shared__ float cf0s[NB][HID], cf1s[NB][HID], cb0s[NB][HID], cb1s[NB][HID];
    __shared__ float gF0[NB][GATES], gF1[NB][GATES];
    __shared__ float gB0[NB][GATES], gB1[NB][GATES];
    __shared__ float xs[NB], xbs[NB];
    __shared__ __align__(16) float wls[2 * HID];
    __shared__ float blin_s;

    u64 w0[16], w1[16], w2[16];
    float bias0, bias1, wx;
    if (isF) {
        load_row(w0, Whh_f0 + j * HID);
        load_row(w1, Wih_f1 + j * HID);
        load_row(w2, Whh_f1 + j * HID);
        bias0 = b_f0[j]; bias1 = b_f1[j]; wx = Wih_f0[j];
    } else {
        load_row(w0, Whh_b0 + j * HID);
        load_row(w1, Wih_b1 + j * HID);
        load_row(w2, Whh_b1 + j * HID);   // on hf1 (replicated bug)
        bias0 = b_b0[j]; bias1 = b_b1[j]; wx = Wih_b0[j];
    }
    const int fut = future_p[0];
    const float *xbase = x + nb0;
    const bool jval = (j < NB) && (nb0 + j < B_TOT);

    for (int i = tid; i < NB * HP; i += 256) {
        ((float *)hf0s)[i] = 0.f; ((float *)hb0s)[i] = 0.f;
    }
    for (int i = tid; i < 2 * NB * HP; i += 256) {
        ((float *)hf1s)[i] = 0.f; ((float *)hb1s)[i] = 0.f;
    }
    for (int i = tid; i < NB * HID; i += 256) {
        ((float *)cf0s)[i] = 0.f; ((float *)cf1s)[i] = 0.f;
        ((float *)cb0s)[i] = 0.f; ((float *)cb1s)[i] = 0.f;
    }
    if (tid < 2 * HID) wls[tid] = Wlin[tid];
    if (tid == 0) blin_s = blin[0];

    int rb = fut % S_LEN; if (rb < 0) rb += S_LEN;     // backward index for t=0

    if (tid < NB) {
        xs[tid] = jval ? xbase[tid] : 0.f;
    } else if (tid >= 128 && tid < 128 + NB) {
        xbs[tid - 128] = jval ? xbase[rb * B_TOT + (tid - 128)] : 0.f;
    }
    rb--; if (rb < 0) rb += S_LEN;                     // index for t=1

    __syncthreads();

    const int m  = j & 31;
    const int ng = j >> 5;

    // prologue: f0_0 from zero state
    if (isF) {
#pragma unroll
        for (int n = 0; n < NB; n++) gF0[n][j] = bias0 + wx * xs[n];
    }
    __syncthreads();
    if (isF) {
        if (ng < 3) cell2(gF0[ng], cf0s[ng], hf0s[ng],
                          gF0[ng + 4], cf0s[ng + 4], hf0s[ng + 4], m);
        else        cell1(gF0[3], cf0s[3], hf0s[3], m);
    }
    if (tid < NB) xs[tid] = jval ? xbase[B_TOT + tid] : 0.f;   // x_1
    __syncthreads();

    // step t computes: f0_{t+1}, f1_t, b0_t, b1_{t-1}, out_{t-2}
    for (int t = 0; t < S_LEN + 2; t++) {
        const int pb = (t + 1) & 1;
        const int cb = t & 1;
        float xreg = 0.f, xbreg = 0.f;

        // ==== compute ====
        if (isF) {
            if (t < S_LEN) {
                if (jval && t + 2 < S_LEN) xreg = xbase[(t + 2) * B_TOT + j];
                const float *hvb = hf1s[pb][0];
#pragma unroll
                for (int n = 0; n < NB; n++) {
                    u64 a0 = 0, a1 = 0, a2 = 0, a3 = 0, a4 = 0, a5 = 0;
                    const ulonglong2 *hu = (const ulonglong2 *)hf0s[n];
                    const ulonglong2 *hv = (const ulonglong2 *)(hvb + n * HP);
#pragma unroll
                    for (int c = 0; c < 8; c++) {
                        ulonglong2 u = hu[c];
                        fma2(a0, w0[2 * c],     u.x);
                        fma2(a1, w0[2 * c + 1], u.y);
                        fma2(a2, w1[2 * c],     u.x);
                        fma2(a3, w1[2 * c + 1], u.y);
                        ulonglong2 v = hv[c];
                        fma2(a4, w2[2 * c],     v.x);
                        fma2(a5, w2[2 * c + 1], v.y);
                    }
                    add2(a0, a1);
                    gF0[n][j] = hsum2(a0) + bias0 + wx * xs[n];     // f0_{t+1}
                    add2(a2, a3); add2(a4, a5); add2(a2, a4);
                    gF1[n][j] = hsum2(a2) + bias1;                  // f1_t
                }
            }
            // out_{t-2}: reads hf1_{t-2} (buf cb) and hb1_{t-2} (buf cb)
            if (t >= 2 && j >= 120) {
                int n = j - 120;
                if (n < NB && nb0 + n < B_TOT) {
                    const ulonglong2 *pf = (const ulonglong2 *)hf1s[cb][n];
                    const ulonglong2 *pk = (const ulonglong2 *)hb1s[cb][n];
                    const ulonglong2 *wf = (const ulonglong2 *)wls;
                    u64 acc = 0, acc2 = 0;
#pragma unroll
                    for (int c = 0; c < 8; c++) {
                        ulonglong2 u = pf[c], wu = wf[c];
                        fma2(acc,  wu.x, u.x);
                        fma2(acc2, wu.y, u.y);
                        ulonglong2 v = pk[c], wv = wf[c + 8];
                        fma2(acc,  wv.x, v.x);
                        fma2(acc2, wv.y, v.y);
                    }
                    add2(acc, acc2);
                    out[(nb0 + n) * S_LEN + (t - 2)] = hsum2(acc) + blin_s;
                }
            }
        } else {
            if (t <= S_LEN) {
                if (jval && t + 1 < S_LEN) xbreg = xbase[rb * B_TOT + j];
                const float *hvb = hf1s[pb][0];
#pragma unroll
                for (int n = 0; n < NB; n++) {
                    u64 a0 = 0, a1 = 0, a2 = 0, a3 = 0, a4 = 0, a5 = 0;
                    const ulonglong2 *hu = (const ulonglong2 *)hb0s[n];
                    const ulonglong2 *hv = (const ulonglong2 *)(hvb + n * HP);
#pragma unroll
                    for (int c = 0; c < 8; c++) {
                        ulonglong2 u = hu[c];
                        fma2(a0, w0[2 * c],     u.x);
                        fma2(a1, w0[2 * c + 1], u.y);
                        fma2(a2, w1[2 * c],     u.x);
                        fma2(a3, w1[2 * c + 1], u.y);
                        ulonglong2 v = hv[c];
                        fma2(a4, w2[2 * c],     v.x);
                        fma2(a5, w2[2 * c + 1], v.y);
                    }
                    add2(a0, a1);
                    gB0[n][j] = hsum2(a0) + bias0 + wx * xbs[n];    // b0_t
                    add2(a2, a3); add2(a4, a5); add2(a2, a4);
                    gB1[n][j] = hsum2(a2) + bias1;                  // b1_{t-1}
                }
            }
            rb--; if (rb < 0) rb += S_LEN;
        }

        // per-half barrier: gates ready within this half
        if (isF) asm volatile("bar.sync 1, 128;" ::: "memory");
        else     asm volatile("bar.sync 2, 128;" ::: "memory");

        // ==== finalize ====
        if (isF) {
            if (t < S_LEN) {
                if (ng < 3) {
                    cell2(gF0[ng], cf0s[ng], hf0s[ng],
                          gF0[ng + 4], cf0s[ng + 4], hf0s[ng + 4], m);         // f0_{t+1}
                    cell2(gF1[ng], cf1s[ng], hf1s[cb][ng],
                          gF1[ng + 4], cf1s[ng + 4], hf1s[cb][ng + 4], m);     // f1_t
                } else {
                    cell2(gF0[3], cf0s[3], hf0s[3],
                          gF1[3], cf1s[3], hf1s[cb][3], m);
                }
                if (j < NB) xs[j] = xreg;                                      // x_{t+2}
            }
        } else {
            if (t < S_LEN) {
                if (ng < 3) cell2(gB0[ng], cb0s[ng], hb0s[ng],
                                  gB0[ng + 4], cb0s[ng + 4], hb0s[ng + 4], m); // b0_t
                else        cell1(gB0[3], cb0s[3], hb0s[3], m);
                if (j < NB) xbs[j] = xbreg;                                    // xb_{t+1}
            }
            if (t >= 1 && t <= S_LEN) {
                if (ng < 3) cell2(gB1[ng], cb1s[ng], hb1s[pb][ng],
                                  gB1[ng + 4], cb1s[ng + 4], hb1s[pb][ng + 4], m); // b1_{t-1}
                else        cell1(gB1[3], cb1s[3], hb1s[pb][3], m);
            }
        }
        __syncthreads();
    }
}

extern "C" void kernel_launch(void *const *d_in, const int *in_sizes, int n_in,
                              void *d_out, int out_size)
{
    const float *x      = (const float *)d_in[0];
    const float *Wih_f0 = (const float *)d_in[1];
    const float *Whh_f0 = (const float *)d_in[2];
    const float *b_f0   = (const float *)d_in[3];
    const float *Wih_f1 = (const float *)d_in[4];
    const float *Whh_f1 = (const float *)d_in[5];
    const float *b_f1   = (const float *)d_in[6];
    const float *Wih_b0 = (const float *)d_in[7];
    const float *Whh_b0 = (const float *)d_in[8];
    const float *b_b0   = (const float *)d_in[9];
    const float *Wih_b1 = (const float *)d_in[10];
    const float *Whh_b1 = (const float *)d_in[11];
    const float *b_b1   = (const float *)d_in[12];
    const float *Wlin   = (const float *)d_in[13];
    const float *blin   = (const float *)d_in[14];
    const int   *future = (const int *)d_in[15];
    float *out = (float *)d_out;

    lstm_kernel<<<NCTA, 256>>>(x,
                               Wih_f0, Whh_f0, b_f0,
                               Wih_f1, Whh_f1, b_f1,
                               Wih_b0, Whh_b0, b_b0,
                               Wih_b1, Whh_b1, b_b1,
                               Wlin, blin, future, out);
}